// round 11
// baseline (speedup 1.0000x reference)
#include <cuda_runtime.h>
#include <math.h>

#define NB 8

__constant__ float c_START_Y[NB] = {0.1f, 0.2f, 0.3f, 0.4f, 0.5f, 0.6f, 0.7f, 0.8f};
__constant__ float c_START_X[NB] = {0.8f, 0.7f, 0.6f, 0.5f, 0.4f, 0.3f, 0.2f, 0.1f};
__constant__ int   c_SIDE[NB]    = {1, 0, 1, 0, 1, 0, 1, 0};

#define MAX_B 4096
__device__ float g_params[NB * MAX_B * 5];

__device__ __forceinline__ float sigmoidf_(float v) {
    return 1.0f / (1.0f + __expf(-v));
}

// ---------------- f32x2 packed helpers (Blackwell FFMA2) --------------------
typedef unsigned long long ull;
__device__ __forceinline__ ull pk2(float x, float y) {
    ull r; asm("mov.b64 %0, {%1,%2};" : "=l"(r) : "f"(x), "f"(y)); return r;
}
__device__ __forceinline__ void upk2(float& x, float& y, ull v) {
    asm("mov.b64 {%0,%1}, %2;" : "=f"(x), "=f"(y) : "l"(v));
}
__device__ __forceinline__ ull fma2(ull a, ull b, ull c) {
    ull d; asm("fma.rn.f32x2 %0, %1, %2, %3;" : "=l"(d) : "l"(a), "l"(b), "l"(c)); return d;
}
__device__ __forceinline__ ull add2(ull a, ull b) {
    ull d; asm("add.rn.f32x2 %0, %1, %2;" : "=l"(d) : "l"(a), "l"(b)); return d;
}
__device__ __forceinline__ ull sub2(ull a, ull b) {
    ull d; asm("sub.rn.f32x2 %0, %1, %2;" : "=l"(d) : "l"(a), "l"(b)); return d;
}

// ---------------------------------------------------------------------------
// Encode: per-blob MLP -> quadratic-form splat coefficients (unchanged, passes)
// ---------------------------------------------------------------------------
__global__ void encode_kernel(const float* __restrict__ positions,
                              const float* __restrict__ W1, const float* __restrict__ b1,
                              const float* __restrict__ W2, const float* __restrict__ b2,
                              const float* __restrict__ W3, const float* __restrict__ b3,
                              const float* __restrict__ scale_ptr, int B)
{
    const int i  = blockIdx.y;
    const int ty = threadIdx.y;
    const int k  = threadIdx.x;
    const int b  = blockIdx.x * 4 + ty;
    const bool valid = (b < B);

    __shared__ float sh_h[4][64];
    __shared__ float sh_bd[4][5];

    float h = 0.0f;
    if (valid) {
        const float* p = positions + (size_t)b * 6 + (c_SIDE[i] ? 0 : 3);
        float p0 = p[0] * 100.0f, p1 = p[1] * 100.0f, p2 = p[2] * 100.0f;
        const float* w1 = W1 + (size_t)i * 3 * 64;
        h = fmaf(p0, w1[k], fmaf(p1, w1[64 + k], fmaf(p2, w1[128 + k], b1[i * 64 + k])));
        h = fmaxf(h, 0.0f);
    }
    sh_h[ty][k] = h;
    __syncthreads();

    float acc = b2[i * 64 + k];
    {
        const float* w2 = W2 + (size_t)i * 64 * 64 + k;
        #pragma unroll 8
        for (int hh = 0; hh < 64; hh++)
            acc = fmaf(sh_h[ty][hh], w2[hh * 64], acc);
        acc = fmaxf(acc, 0.0f);
    }
    __syncthreads();
    sh_h[ty][k] = acc;
    __syncthreads();

    if (k < 5) {
        float o = b3[i * 5 + k];
        const float* w3 = W3 + (size_t)i * 64 * 5 + k;
        #pragma unroll 8
        for (int hh = 0; hh < 64; hh++)
            o = fmaf(sh_h[ty][hh], w3[hh * 5], o);
        sh_bd[ty][k] = o;
    }
    __syncthreads();

    if (k == 0 && valid) {
        float bd0 = sh_bd[ty][0], bd1 = sh_bd[ty][1], bd2 = sh_bd[ty][2];
        float bd3 = sh_bd[ty][3], bd4 = sh_bd[ty][4];
        float scale = *scale_ptr;

        float y  = sigmoidf_(bd0) + c_START_Y[i];
        float x  = sigmoidf_(bd1) + c_START_X[i];
        float s  = (bd2 + 0.05f) * scale;
        float a  = 0.5f + sigmoidf_(bd3) * 1.5f;
        float th = sigmoidf_(bd4) * 3.14159265358979323846f;

        float sa = s * a + 1e-6f;
        float sb = s / (a + 1e-6f) + 1e-6f;
        float A  = 0.5f / (sa * sa);
        float Bq = 0.5f / (sb * sb);

        float sn, c;
        sincosf(th, &sn, &c);

        const float L = 1.4426950408889634f;
        float al = -L * (A * c * c + Bq * sn * sn);
        float be = -L * (A * sn * sn + Bq * c * c);
        float ga = -2.0f * L * (A - Bq) * c * sn;

        float* o = g_params + ((size_t)i * B + b) * 5;
        o[0] = y; o[1] = x; o[2] = al; o[3] = be; o[4] = ga;
    }
}

// ---------------------------------------------------------------------------
// Splat, suffix-sum form:  img(w) = sum_{j=0..7} exp2(S_j(w)),
// S_j = suffix sum of per-blob quadratics (exact identity for the sequential
// blend img = img*cur + cur). Term j=0 (the full sum) is evaluated on the
// FMA/ALU pipes (magic range reduction + deg-3 poly + exponent-bit merge);
// terms 1..7 use scalar MUFU ex2. Scalar core, no pack/unpack in the MUFU
// path; launch_bounds(256,6) for 48 warps/SM.
// ---------------------------------------------------------------------------

// deg-3 economized poly for 2^f on f in [-0.5,0.5]  (rel err ~1.2e-4)
#define E3C0 0.9999248720f
#define E3C1 0.6931471806f
#define E3C2 0.2426310393f
#define E3C3 0.0555041087f

#define MAGIC 12582912.0f   // 1.5 * 2^23

template<int NC>
__global__ void __launch_bounds__(256, 6) splat_fast(float* __restrict__ out,
                                                     int B, int T, float invT)
{
    const int b    = blockIdx.y;
    const int tid  = threadIdx.x;
    const int lane = tid & 31;
    const int r    = tid >> 5;
    const int row  = blockIdx.x * 8 + r;

    __shared__ float sp[NB * 5];
    if (tid < NB * 5) {
        int i = tid / 5, f = tid - i * 5;
        sp[tid] = g_params[((size_t)i * B + b) * 5 + f];
    }
    __syncthreads();
    if (row >= T) return;

    const float rowc = ((float)row + 0.5f) * invT;

    // per-blob row quadratic e_i(w) = K2 w^2 + K1 w + K0, then suffix sums
    float K2s[NB], K1s[NB], K0s[NB];
    #pragma unroll
    for (int i = 0; i < NB; i++) {
        float y  = sp[i * 5 + 0];
        float x  = sp[i * 5 + 1];
        float al = sp[i * 5 + 2];
        float be = sp[i * 5 + 3];
        float ga = sp[i * 5 + 4];
        float dy = rowc - y;
        K2s[i] = be;
        K1s[i] = fmaf(ga, dy, -2.0f * be * x);
        float m = fmaf(al, dy, -(ga * x));
        K0s[i] = fmaf(m, dy, be * x * x);
    }
    #pragma unroll
    for (int i = NB - 2; i >= 0; i--) {
        K2s[i] += K2s[i + 1];
        K1s[i] += K1s[i + 1];
        K0s[i] += K0s[i + 1];
    }

    // term 0 (full sum) packed for the FMA-pipe exp2
    const ull q2 = pk2(K2s[0], K2s[0]);
    const ull q1 = pk2(K1s[0], K1s[0]);
    const ull q0 = pk2(K0s[0], K0s[0]);
    const ull M2 = pk2(MAGIC, MAGIC);
    const ull P3 = pk2(E3C3, E3C3), P2 = pk2(E3C2, E3C2);
    const ull P1 = pk2(E3C1, E3C1), P0 = pk2(E3C0, E3C0);

    float2* orow = reinterpret_cast<float2*>(out + ((size_t)b * T + row) * T);

    const float wbase = ((float)(2 * lane) + 0.5f) * invT;
    const float wstep = 64.0f * invT;

    #pragma unroll 1
    for (int c = 0; c < NC; c++) {
        float wA = fmaf((float)c, wstep, wbase);
        float wB = wA + invT;

        // ---- term 0 on FMA/ALU pipes ----
        ull wP = pk2(wA, wB);
        ull e  = fma2(fma2(q2, wP, q1), wP, q0);
        float eA, eB;
        upk2(eA, eB, e);
        eA = fmaxf(eA, -126.0f);               // guards sigma->0 blobs
        eB = fmaxf(eB, -126.0f);
        ull ec = pk2(eA, eB);
        ull t  = add2(ec, M2);                 // MAGIC + round(e)
        ull kf = sub2(t, M2);                  // k = round(e), exact
        ull f  = sub2(ec, kf);                 // f in [-0.5,0.5], exact
        ull p  = fma2(P3, f, P2);
        p = fma2(p, f, P1);
        p = fma2(p, f, P0);                    // 2^f in [0.70, 1.42]
        float pA, pB, tA, tB;
        upk2(pA, pB, p);
        upk2(tA, tB, t);
        float imgA = __uint_as_float(__float_as_uint(pA) + (__float_as_uint(tA) << 23));
        float imgB = __uint_as_float(__float_as_uint(pB) + (__float_as_uint(tB) << 23));

        // ---- terms 1..7 on MUFU, fully scalar ----
        #pragma unroll
        for (int i = 1; i < NB; i++) {
            float eA_ = fmaf(fmaf(K2s[i], wA, K1s[i]), wA, K0s[i]);
            float eB_ = fmaf(fmaf(K2s[i], wB, K1s[i]), wB, K0s[i]);
            float cA_, cB_;
            asm("ex2.approx.ftz.f32 %0, %1;" : "=f"(cA_) : "f"(eA_));
            asm("ex2.approx.ftz.f32 %0, %1;" : "=f"(cB_) : "f"(eB_));
            imgA += cA_;
            imgB += cB_;
        }

        orow[c * 32 + lane] = make_float2(imgA, imgB);
    }
}

// ---------------------------------------------------------------------------
// Generic fallback splat (round-2 kernel, known correct for any T).
// ---------------------------------------------------------------------------
__global__ void __launch_bounds__(256) splat_kernel(float* __restrict__ out,
                                                    int B, int T, float invT)
{
    const int b    = blockIdx.y;
    const int tid  = threadIdx.x;
    const int lane = tid & 31;
    const int r    = tid >> 5;
    const int row  = blockIdx.x * 8 + r;

    __shared__ float sp[NB * 5];
    if (tid < NB * 5) {
        int i = tid / 5, f = tid - i * 5;
        sp[tid] = g_params[((size_t)i * B + b) * 5 + f];
    }
    __syncthreads();
    if (row >= T) return;

    const float rowc = ((float)row + 0.5f) * invT;

    float K2[NB], K1[NB], K0[NB];
    #pragma unroll
    for (int i = 0; i < NB; i++) {
        float y  = sp[i * 5 + 0];
        float x  = sp[i * 5 + 1];
        float al = sp[i * 5 + 2];
        float be = sp[i * 5 + 3];
        float ga = sp[i * 5 + 4];
        float dy = rowc - y;
        K2[i] = be;
        K1[i] = fmaf(ga, dy, -2.0f * be * x);
        float m = fmaf(al, dy, -(ga * x));
        K0[i] = fmaf(m, dy, be * x * x);
    }

    float* orow = out + ((size_t)b * T + row) * T;
    const int nj = (T + 31) >> 5;

    for (int j = 0; j < nj; j++) {
        int col = lane + (j << 5);
        if (col >= T) break;
        float w = ((float)col + 0.5f) * invT;
        float img = 0.0f;
        #pragma unroll
        for (int i = 0; i < NB; i++) {
            float e = fmaf(fmaf(K2[i], w, K1[i]), w, K0[i]);
            float cur;
            asm("ex2.approx.ftz.f32 %0, %1;" : "=f"(cur) : "f"(e));
            img = fmaf(img, cur, cur);
        }
        orow[col] = img;
    }
}

// ---------------------------------------------------------------------------
extern "C" void kernel_launch(void* const* d_in, const int* in_sizes, int n_in,
                              void* d_out, int out_size)
{
    const float* positions = (const float*)d_in[0];
    const float* W1 = (const float*)d_in[1];
    const float* b1 = (const float*)d_in[2];
    const float* W2 = (const float*)d_in[3];
    const float* b2 = (const float*)d_in[4];
    const float* W3 = (const float*)d_in[5];
    const float* b3 = (const float*)d_in[6];
    const float* scale = (const float*)d_in[n_in - 1];

    int B = in_sizes[0] / 6;
    if (B > MAX_B) B = MAX_B;
    int T = (int)(sqrt((double)out_size / (double)B) + 0.5);
    float invT = 1.0f / (float)T;

    dim3 egrid((B + 3) / 4, NB);
    dim3 eblock(64, 4);
    encode_kernel<<<egrid, eblock>>>(positions, W1, b1, W2, b2, W3, b3, scale, B);

    dim3 sgrid((T + 7) / 8, B);
    if (T == 256)
        splat_fast<4><<<sgrid, 256>>>((float*)d_out, B, T, invT);
    else if (T == 128)
        splat_fast<2><<<sgrid, 256>>>((float*)d_out, B, T, invT);
    else
        splat_kernel<<<sgrid, 256>>>((float*)d_out, B, T, invT);
}

// round 12
// speedup vs baseline: 1.2219x; 1.2219x over previous
#include <cuda_runtime.h>
#include <math.h>

#define NB 8

__constant__ float c_START_Y[NB] = {0.1f, 0.2f, 0.3f, 0.4f, 0.5f, 0.6f, 0.7f, 0.8f};
__constant__ float c_START_X[NB] = {0.8f, 0.7f, 0.6f, 0.5f, 0.4f, 0.3f, 0.2f, 0.1f};
__constant__ int   c_SIDE[NB]    = {1, 0, 1, 0, 1, 0, 1, 0};

#define MAX_B 4096
__device__ float g_params[NB * MAX_B * 5];

__device__ __forceinline__ float sigmoidf_(float v) {
    return 1.0f / (1.0f + __expf(-v));
}

// ---------------- f32x2 packed helpers (Blackwell FFMA2) --------------------
typedef unsigned long long ull;
__device__ __forceinline__ ull pk2(float x, float y) {
    ull r; asm("mov.b64 %0, {%1,%2};" : "=l"(r) : "f"(x), "f"(y)); return r;
}
__device__ __forceinline__ void upk2(float& x, float& y, ull v) {
    asm("mov.b64 {%0,%1}, %2;" : "=f"(x), "=f"(y) : "l"(v));
}
__device__ __forceinline__ ull fma2(ull a, ull b, ull c) {
    ull d; asm("fma.rn.f32x2 %0, %1, %2, %3;" : "=l"(d) : "l"(a), "l"(b), "l"(c)); return d;
}

// ---------------------------------------------------------------------------
// Encode: per-blob MLP -> quadratic-form splat coefficients
// (same structure as the passing version; sincosf -> __sinf/__cosf)
// ---------------------------------------------------------------------------
__global__ void encode_kernel(const float* __restrict__ positions,
                              const float* __restrict__ W1, const float* __restrict__ b1,
                              const float* __restrict__ W2, const float* __restrict__ b2,
                              const float* __restrict__ W3, const float* __restrict__ b3,
                              const float* __restrict__ scale_ptr, int B)
{
    const int i  = blockIdx.y;
    const int ty = threadIdx.y;
    const int k  = threadIdx.x;
    const int b  = blockIdx.x * 4 + ty;
    const bool valid = (b < B);

    __shared__ float sh_h[4][64];
    __shared__ float sh_bd[4][5];

    float h = 0.0f;
    if (valid) {
        const float* p = positions + (size_t)b * 6 + (c_SIDE[i] ? 0 : 3);
        float p0 = p[0] * 100.0f, p1 = p[1] * 100.0f, p2 = p[2] * 100.0f;
        const float* w1 = W1 + (size_t)i * 3 * 64;
        h = fmaf(p0, w1[k], fmaf(p1, w1[64 + k], fmaf(p2, w1[128 + k], b1[i * 64 + k])));
        h = fmaxf(h, 0.0f);
    }
    sh_h[ty][k] = h;
    __syncthreads();

    float acc = b2[i * 64 + k];
    {
        const float* w2 = W2 + (size_t)i * 64 * 64 + k;
        #pragma unroll 8
        for (int hh = 0; hh < 64; hh++)
            acc = fmaf(sh_h[ty][hh], w2[hh * 64], acc);
        acc = fmaxf(acc, 0.0f);
    }
    __syncthreads();
    sh_h[ty][k] = acc;
    __syncthreads();

    if (k < 5) {
        float o = b3[i * 5 + k];
        const float* w3 = W3 + (size_t)i * 64 * 5 + k;
        #pragma unroll 8
        for (int hh = 0; hh < 64; hh++)
            o = fmaf(sh_h[ty][hh], w3[hh * 5], o);
        sh_bd[ty][k] = o;
    }
    __syncthreads();

    if (k == 0 && valid) {
        float bd0 = sh_bd[ty][0], bd1 = sh_bd[ty][1], bd2 = sh_bd[ty][2];
        float bd3 = sh_bd[ty][3], bd4 = sh_bd[ty][4];
        float scale = *scale_ptr;

        float y  = sigmoidf_(bd0) + c_START_Y[i];
        float x  = sigmoidf_(bd1) + c_START_X[i];
        float s  = (bd2 + 0.05f) * scale;
        float a  = 0.5f + sigmoidf_(bd3) * 1.5f;
        float th = sigmoidf_(bd4) * 3.14159265358979323846f;

        float sa = s * a + 1e-6f;
        float sb = s / (a + 1e-6f) + 1e-6f;
        float A  = 0.5f / (sa * sa);
        float Bq = 0.5f / (sb * sb);

        float sn = __sinf(th);          // th in [0, pi] — fast path, abs err ~1e-6
        float c  = __cosf(th);

        const float L = 1.4426950408889634f;
        float al = -L * (A * c * c + Bq * sn * sn);
        float be = -L * (A * sn * sn + Bq * c * c);
        float ga = -2.0f * L * (A - Bq) * c * sn;

        float* o = g_params + ((size_t)i * B + b) * 5;
        o[0] = y; o[1] = x; o[2] = al; o[3] = be; o[4] = ga;
    }
}

// ---------------------------------------------------------------------------
// Splat (R9, best-known: 28.35us): warp = row, lane = one f32x2 pixel pair,
// NC chunks of 64 px, pure MUFU exp2, packed coefficients hoisted per row.
// Added: grid-dependency sync for PDL overlap with encode.
// ---------------------------------------------------------------------------
template<int NC>
__global__ void __launch_bounds__(256, 4) splat_fast(float* __restrict__ out,
                                                     int B, int T, float invT)
{
    cudaGridDependencySynchronize();   // PDL: wait for encode's g_params

    const int b    = blockIdx.y;
    const int tid  = threadIdx.x;
    const int lane = tid & 31;
    const int r    = tid >> 5;
    const int row  = blockIdx.x * 8 + r;

    __shared__ float sp[NB * 5];
    if (tid < NB * 5) {
        int i = tid / 5, f = tid - i * 5;
        sp[tid] = g_params[((size_t)i * B + b) * 5 + f];
    }
    __syncthreads();
    if (row >= T) return;

    const float rowc = ((float)row + 0.5f) * invT;

    // per-blob row quadratic e(w) = K2 w^2 + K1 w + K0  (e <= 0), warp-uniform,
    // packed once per row (hoisted out of the pixel loop).
    ull k2p[NB], k1p[NB], k0p[NB];
    #pragma unroll
    for (int i = 0; i < NB; i++) {
        float y  = sp[i * 5 + 0];
        float x  = sp[i * 5 + 1];
        float al = sp[i * 5 + 2];
        float be = sp[i * 5 + 3];
        float ga = sp[i * 5 + 4];
        float dy = rowc - y;
        float K2 = be;
        float K1 = fmaf(ga, dy, -2.0f * be * x);
        float m  = fmaf(al, dy, -(ga * x));
        float K0 = fmaf(m, dy, be * x * x);
        k2p[i] = pk2(K2, K2);
        k1p[i] = pk2(K1, K1);
        k0p[i] = pk2(K0, K0);
    }

    float2* orow = reinterpret_cast<float2*>(out + ((size_t)b * T + row) * T);

    const float wbase = ((float)(2 * lane) + 0.5f) * invT;
    const float wstep = 64.0f * invT;

    #pragma unroll 1
    for (int c = 0; c < NC; c++) {
        float w0 = fmaf((float)c, wstep, wbase);
        ull w   = pk2(w0, w0 + invT);
        ull img = 0ull;

        #pragma unroll
        for (int i = 0; i < NB; i++) {
            ull e = fma2(fma2(k2p[i], w, k1p[i]), w, k0p[i]);
            float ex, ey, cx, cy;
            upk2(ex, ey, e);
            asm("ex2.approx.ftz.f32 %0, %1;" : "=f"(cx) : "f"(ex));
            asm("ex2.approx.ftz.f32 %0, %1;" : "=f"(cy) : "f"(ey));
            ull cur = pk2(cx, cy);
            img = fma2(img, cur, cur);          // reference blend order
        }

        float ix, iy;
        upk2(ix, iy, img);
        orow[c * 32 + lane] = make_float2(ix, iy);
    }
}

// ---------------------------------------------------------------------------
// Generic fallback splat (round-2 kernel, known correct for any T).
// ---------------------------------------------------------------------------
__global__ void __launch_bounds__(256) splat_kernel(float* __restrict__ out,
                                                    int B, int T, float invT)
{
    cudaGridDependencySynchronize();

    const int b    = blockIdx.y;
    const int tid  = threadIdx.x;
    const int lane = tid & 31;
    const int r    = tid >> 5;
    const int row  = blockIdx.x * 8 + r;

    __shared__ float sp[NB * 5];
    if (tid < NB * 5) {
        int i = tid / 5, f = tid - i * 5;
        sp[tid] = g_params[((size_t)i * B + b) * 5 + f];
    }
    __syncthreads();
    if (row >= T) return;

    const float rowc = ((float)row + 0.5f) * invT;

    float K2[NB], K1[NB], K0[NB];
    #pragma unroll
    for (int i = 0; i < NB; i++) {
        float y  = sp[i * 5 + 0];
        float x  = sp[i * 5 + 1];
        float al = sp[i * 5 + 2];
        float be = sp[i * 5 + 3];
        float ga = sp[i * 5 + 4];
        float dy = rowc - y;
        K2[i] = be;
        K1[i] = fmaf(ga, dy, -2.0f * be * x);
        float m = fmaf(al, dy, -(ga * x));
        K0[i] = fmaf(m, dy, be * x * x);
    }

    float* orow = out + ((size_t)b * T + row) * T;
    const int nj = (T + 31) >> 5;

    for (int j = 0; j < nj; j++) {
        int col = lane + (j << 5);
        if (col >= T) break;
        float w = ((float)col + 0.5f) * invT;
        float img = 0.0f;
        #pragma unroll
        for (int i = 0; i < NB; i++) {
            float e = fmaf(fmaf(K2[i], w, K1[i]), w, K0[i]);
            float cur;
            asm("ex2.approx.ftz.f32 %0, %1;" : "=f"(cur) : "f"(e));
            img = fmaf(img, cur, cur);
        }
        orow[col] = img;
    }
}

// ---------------------------------------------------------------------------
extern "C" void kernel_launch(void* const* d_in, const int* in_sizes, int n_in,
                              void* d_out, int out_size)
{
    const float* positions = (const float*)d_in[0];
    const float* W1 = (const float*)d_in[1];
    const float* b1 = (const float*)d_in[2];
    const float* W2 = (const float*)d_in[3];
    const float* b2 = (const float*)d_in[4];
    const float* W3 = (const float*)d_in[5];
    const float* b3 = (const float*)d_in[6];
    const float* scale = (const float*)d_in[n_in - 1];

    int B = in_sizes[0] / 6;
    if (B > MAX_B) B = MAX_B;
    int T = (int)(sqrt((double)out_size / (double)B) + 0.5);
    float invT = 1.0f / (float)T;

    dim3 egrid((B + 3) / 4, NB);
    dim3 eblock(64, 4);
    encode_kernel<<<egrid, eblock>>>(positions, W1, b1, W2, b2, W3, b3, scale, B);

    dim3 sgrid((T + 7) / 8, B);

    // PDL launch: splat overlaps encode; dependency resolved by
    // cudaGridDependencySynchronize() inside the kernel.
    cudaLaunchAttribute attrs[1];
    attrs[0].id = cudaLaunchAttributeProgrammaticStreamSerialization;
    attrs[0].val.programmaticStreamSerializationAllowed = 1;

    cudaLaunchConfig_t cfg = {};
    cfg.gridDim = sgrid;
    cfg.blockDim = dim3(256, 1, 1);
    cfg.dynamicSmemBytes = 0;
    cfg.stream = 0;
    cfg.attrs = attrs;
    cfg.numAttrs = 1;

    if (T == 256)
        cudaLaunchKernelEx(&cfg, splat_fast<4>, (float*)d_out, B, T, invT);
    else if (T == 128)
        cudaLaunchKernelEx(&cfg, splat_fast<2>, (float*)d_out, B, T, invT);
    else
        cudaLaunchKernelEx(&cfg, splat_kernel, (float*)d_out, B, T, invT);
}

// round 13
// speedup vs baseline: 1.4298x; 1.1702x over previous
#include <cuda_runtime.h>
#include <math.h>

#define NB 8

__constant__ float c_START_Y[NB] = {0.1f, 0.2f, 0.3f, 0.4f, 0.5f, 0.6f, 0.7f, 0.8f};
__constant__ float c_START_X[NB] = {0.8f, 0.7f, 0.6f, 0.5f, 0.4f, 0.3f, 0.2f, 0.1f};
__constant__ int   c_SIDE[NB]    = {1, 0, 1, 0, 1, 0, 1, 0};

#define MAX_B 4096
__device__ float g_params[NB * MAX_B * 5];

__device__ __forceinline__ float sigmoidf_(float v) {
    return 1.0f / (1.0f + __expf(-v));
}

// ---------------- f32x2 packed helpers (Blackwell) --------------------------
typedef unsigned long long ull;
__device__ __forceinline__ ull pk2(float x, float y) {
    ull r; asm("mov.b64 %0, {%1,%2};" : "=l"(r) : "f"(x), "f"(y)); return r;
}
__device__ __forceinline__ void upk2(float& x, float& y, ull v) {
    asm("mov.b64 {%0,%1}, %2;" : "=f"(x), "=f"(y) : "l"(v));
}
__device__ __forceinline__ ull fma2(ull a, ull b, ull c) {
    ull d; asm("fma.rn.f32x2 %0, %1, %2, %3;" : "=l"(d) : "l"(a), "l"(b), "l"(c)); return d;
}
__device__ __forceinline__ ull mul2(ull a, ull b) {
    ull d; asm("mul.rn.f32x2 %0, %1, %2;" : "=l"(d) : "l"(a), "l"(b)); return d;
}
__device__ __forceinline__ float ex2_(float v) {
    float r; asm("ex2.approx.ftz.f32 %0, %1;" : "=f"(r) : "f"(v)); return r;
}

// ---------------------------------------------------------------------------
// Encode: per-blob MLP -> quadratic-form splat coefficients (R12, passed 3.2e-7)
// ---------------------------------------------------------------------------
__global__ void encode_kernel(const float* __restrict__ positions,
                              const float* __restrict__ W1, const float* __restrict__ b1,
                              const float* __restrict__ W2, const float* __restrict__ b2,
                              const float* __restrict__ W3, const float* __restrict__ b3,
                              const float* __restrict__ scale_ptr, int B)
{
    const int i  = blockIdx.y;
    const int ty = threadIdx.y;
    const int k  = threadIdx.x;
    const int b  = blockIdx.x * 4 + ty;
    const bool valid = (b < B);

    __shared__ float sh_h[4][64];
    __shared__ float sh_bd[4][5];

    float h = 0.0f;
    if (valid) {
        const float* p = positions + (size_t)b * 6 + (c_SIDE[i] ? 0 : 3);
        float p0 = p[0] * 100.0f, p1 = p[1] * 100.0f, p2 = p[2] * 100.0f;
        const float* w1 = W1 + (size_t)i * 3 * 64;
        h = fmaf(p0, w1[k], fmaf(p1, w1[64 + k], fmaf(p2, w1[128 + k], b1[i * 64 + k])));
        h = fmaxf(h, 0.0f);
    }
    sh_h[ty][k] = h;
    __syncthreads();

    float acc = b2[i * 64 + k];
    {
        const float* w2 = W2 + (size_t)i * 64 * 64 + k;
        #pragma unroll 8
        for (int hh = 0; hh < 64; hh++)
            acc = fmaf(sh_h[ty][hh], w2[hh * 64], acc);
        acc = fmaxf(acc, 0.0f);
    }
    __syncthreads();
    sh_h[ty][k] = acc;
    __syncthreads();

    if (k < 5) {
        float o = b3[i * 5 + k];
        const float* w3 = W3 + (size_t)i * 64 * 5 + k;
        #pragma unroll 8
        for (int hh = 0; hh < 64; hh++)
            o = fmaf(sh_h[ty][hh], w3[hh * 5], o);
        sh_bd[ty][k] = o;
    }
    __syncthreads();

    if (k == 0 && valid) {
        float bd0 = sh_bd[ty][0], bd1 = sh_bd[ty][1], bd2 = sh_bd[ty][2];
        float bd3 = sh_bd[ty][3], bd4 = sh_bd[ty][4];
        float scale = *scale_ptr;

        float y  = sigmoidf_(bd0) + c_START_Y[i];
        float x  = sigmoidf_(bd1) + c_START_X[i];
        float s  = (bd2 + 0.05f) * scale;
        float a  = 0.5f + sigmoidf_(bd3) * 1.5f;
        float th = sigmoidf_(bd4) * 3.14159265358979323846f;

        float sa = s * a + 1e-6f;
        float sb = s / (a + 1e-6f) + 1e-6f;
        float A  = 0.5f / (sa * sa);
        float Bq = 0.5f / (sb * sb);

        float sn = __sinf(th);          // th in [0, pi]
        float c  = __cosf(th);

        const float L = 1.4426950408889634f;
        float al = -L * (A * c * c + Bq * sn * sn);
        float be = -L * (A * sn * sn + Bq * c * c);
        float ga = -2.0f * L * (A - Bq) * c * sn;

        float* o = g_params + ((size_t)i * B + b) * 5;
        o[0] = y; o[1] = x; o[2] = al; o[3] = be; o[4] = ga;
    }
}

// ---------------------------------------------------------------------------
// Splat via multiplicative forward recurrence (T = 256 only).
//   g(w)      = 2^{e(w)},  e quadratic (K2<0)
//   g(w+2D)   = g(w) * m(w),   m(w) = 2^{d(w)},  d(w) = qd*w + cd   (linear)
//   m(w+2D)   = m(w) * rho,    rho  = 2^{8*K2*D^2}  (<= 1 since K2 < 0)
// Warp = 2 rows; lane16 owns 16 contiguous px = 8 f32x2 pairs.
// Per blob per lane: 4 EX2 seeds + 14 MUL2 + 8 FMA2 blend. EX2/px: 8 -> 0.5.
// ---------------------------------------------------------------------------
__global__ void __launch_bounds__(256) splat_rec256(float* __restrict__ out,
                                                    int B, int T, float invT)
{
    const int b   = blockIdx.y;
    const int tid = threadIdx.x;

    __shared__ float  sp[NB * 5];
    __shared__ float4 rowtab[16][NB];   // {K1, K0, cd, K2} per (row-in-block, blob)
    __shared__ float4 blobtab[NB];      // {qd, 0, rho, rho} per blob

    if (tid < NB * 5) {
        int i = tid / 5, f = tid - i * 5;
        sp[tid] = g_params[((size_t)i * B + b) * 5 + f];
    }
    __syncthreads();

    if (tid < 128) {
        const int r = tid >> 3;          // row-in-block 0..15
        const int i = tid & 7;           // blob
        float y  = sp[i * 5 + 0];
        float x  = sp[i * 5 + 1];
        float al = sp[i * 5 + 2];
        float be = sp[i * 5 + 3];
        float ga = sp[i * 5 + 4];
        float rowc = ((float)(blockIdx.x * 16 + r) + 0.5f) * invT;
        float dy = rowc - y;
        float K2 = be;
        float K1 = fmaf(ga, dy, -2.0f * be * x);
        float mm = fmaf(al, dy, -(ga * x));
        float K0 = fmaf(mm, dy, be * x * x);
        // d(w) = e(w+2D) - e(w) = (4 K2 D) w + (4 K2 D^2 + 2 K1 D)
        float cd = fmaf(4.0f * K2 * invT, invT, 2.0f * K1 * invT);
        rowtab[r][i] = make_float4(K1, K0, cd, K2);
        if (r == 0) {
            float qd  = 4.0f * K2 * invT;
            float rho = exp2f(8.0f * K2 * invT * invT);   // in (0, 1]
            blobtab[i] = make_float4(qd, 0.0f, rho, rho);
        }
    }
    __syncthreads();

    const int lane   = tid & 31;
    const int rr     = ((tid >> 5) << 1) | (lane >> 4);   // row-in-block 0..15
    const int lane16 = lane & 15;
    const int row    = blockIdx.x * 16 + rr;
    const int seg    = lane16 * 16;                       // first pixel of segment

    const float w0 = ((float)seg + 0.5f) * invT;
    const float w1 = w0 + invT;

    ull img[8];
    #pragma unroll
    for (int k = 0; k < 8; k++) img[k] = 0ull;

    #pragma unroll
    for (int i = 0; i < NB; i++) {
        float4 rt = rowtab[rr][i];       // K1, K0, cd, K2
        float4 bt = blobtab[i];          // qd, -, rho, rho

        float e0 = fmaf(fmaf(rt.w, w0, rt.x), w0, rt.y);
        float e1 = fmaf(fmaf(rt.w, w1, rt.x), w1, rt.y);
        float d0 = fminf(fmaf(bt.x, w0, rt.z), 126.0f);   // clamp: no inf -> no NaN
        float d1 = fminf(fmaf(bt.x, w1, rt.z), 126.0f);

        ull g   = pk2(ex2_(e0), ex2_(e1));
        ull m   = pk2(ex2_(d0), ex2_(d1));
        ull rho = pk2(bt.z, bt.w);

        #pragma unroll
        for (int k = 0; k < 8; k++) {
            img[k] = fma2(img[k], g, g);      // reference blend order
            if (k < 7) {
                g = mul2(g, m);
                m = mul2(m, rho);
            }
        }
    }

    float* orow = out + ((size_t)b * T + row) * T + seg;
    #pragma unroll
    for (int j = 0; j < 4; j++) {
        float x0, x1, x2, x3;
        upk2(x0, x1, img[2 * j]);
        upk2(x2, x3, img[2 * j + 1]);
        reinterpret_cast<float4*>(orow)[j] = make_float4(x0, x1, x2, x3);
    }
}

// ---------------------------------------------------------------------------
// Generic fallback splat (round-2 kernel, known correct for any T).
// ---------------------------------------------------------------------------
__global__ void __launch_bounds__(256) splat_kernel(float* __restrict__ out,
                                                    int B, int T, float invT)
{
    const int b    = blockIdx.y;
    const int tid  = threadIdx.x;
    const int lane = tid & 31;
    const int r    = tid >> 5;
    const int row  = blockIdx.x * 8 + r;

    __shared__ float sp[NB * 5];
    if (tid < NB * 5) {
        int i = tid / 5, f = tid - i * 5;
        sp[tid] = g_params[((size_t)i * B + b) * 5 + f];
    }
    __syncthreads();
    if (row >= T) return;

    const float rowc = ((float)row + 0.5f) * invT;

    float K2[NB], K1[NB], K0[NB];
    #pragma unroll
    for (int i = 0; i < NB; i++) {
        float y  = sp[i * 5 + 0];
        float x  = sp[i * 5 + 1];
        float al = sp[i * 5 + 2];
        float be = sp[i * 5 + 3];
        float ga = sp[i * 5 + 4];
        float dy = rowc - y;
        K2[i] = be;
        K1[i] = fmaf(ga, dy, -2.0f * be * x);
        float m = fmaf(al, dy, -(ga * x));
        K0[i] = fmaf(m, dy, be * x * x);
    }

    float* orow = out + ((size_t)b * T + row) * T;
    const int nj = (T + 31) >> 5;

    for (int j = 0; j < nj; j++) {
        int col = lane + (j << 5);
        if (col >= T) break;
        float w = ((float)col + 0.5f) * invT;
        float img = 0.0f;
        #pragma unroll
        for (int i = 0; i < NB; i++) {
            float e = fmaf(fmaf(K2[i], w, K1[i]), w, K0[i]);
            float cur = ex2_(e);
            img = fmaf(img, cur, cur);
        }
        orow[col] = img;
    }
}

// ---------------------------------------------------------------------------
extern "C" void kernel_launch(void* const* d_in, const int* in_sizes, int n_in,
                              void* d_out, int out_size)
{
    const float* positions = (const float*)d_in[0];
    const float* W1 = (const float*)d_in[1];
    const float* b1 = (const float*)d_in[2];
    const float* W2 = (const float*)d_in[3];
    const float* b2 = (const float*)d_in[4];
    const float* W3 = (const float*)d_in[5];
    const float* b3 = (const float*)d_in[6];
    const float* scale = (const float*)d_in[n_in - 1];

    int B = in_sizes[0] / 6;
    if (B > MAX_B) B = MAX_B;
    int T = (int)(sqrt((double)out_size / (double)B) + 0.5);
    float invT = 1.0f / (float)T;

    dim3 egrid((B + 3) / 4, NB);
    dim3 eblock(64, 4);
    encode_kernel<<<egrid, eblock>>>(positions, W1, b1, W2, b2, W3, b3, scale, B);

    if (T == 256) {
        dim3 sgrid(16, B);                // 16 rows per block
        splat_rec256<<<sgrid, 256>>>((float*)d_out, B, T, invT);
    } else {
        dim3 sgrid((T + 7) / 8, B);
        splat_kernel<<<sgrid, 256>>>((float*)d_out, B, T, invT);
    }
}

// round 14
// speedup vs baseline: 1.6305x; 1.1404x over previous
#include <cuda_runtime.h>
#include <math.h>

#define NB 8

__constant__ float c_START_Y[NB] = {0.1f, 0.2f, 0.3f, 0.4f, 0.5f, 0.6f, 0.7f, 0.8f};
__constant__ float c_START_X[NB] = {0.8f, 0.7f, 0.6f, 0.5f, 0.4f, 0.3f, 0.2f, 0.1f};
__constant__ int   c_SIDE[NB]    = {1, 0, 1, 0, 1, 0, 1, 0};

#define MAX_B 4096
__device__ float g_params[NB * MAX_B * 5];

__device__ __forceinline__ float sigmoidf_(float v) {
    return 1.0f / (1.0f + __expf(-v));
}

// ---------------- f32x2 packed helpers (Blackwell) --------------------------
typedef unsigned long long ull;
__device__ __forceinline__ ull pk2(float x, float y) {
    ull r; asm("mov.b64 %0, {%1,%2};" : "=l"(r) : "f"(x), "f"(y)); return r;
}
__device__ __forceinline__ void upk2(float& x, float& y, ull v) {
    asm("mov.b64 {%0,%1}, %2;" : "=f"(x), "=f"(y) : "l"(v));
}
__device__ __forceinline__ ull fma2(ull a, ull b, ull c) {
    ull d; asm("fma.rn.f32x2 %0, %1, %2, %3;" : "=l"(d) : "l"(a), "l"(b), "l"(c)); return d;
}
__device__ __forceinline__ ull mul2(ull a, ull b) {
    ull d; asm("mul.rn.f32x2 %0, %1, %2;" : "=l"(d) : "l"(a), "l"(b)); return d;
}
__device__ __forceinline__ float ex2_(float v) {
    float r; asm("ex2.approx.ftz.f32 %0, %1;" : "=f"(r) : "f"(v)); return r;
}

// ---------------------------------------------------------------------------
// Encode: per-blob MLP -> quadratic-form splat coefficients
// (R13-passing structure; dual accumulators in layers 2/3)
// ---------------------------------------------------------------------------
__global__ void encode_kernel(const float* __restrict__ positions,
                              const float* __restrict__ W1, const float* __restrict__ b1,
                              const float* __restrict__ W2, const float* __restrict__ b2,
                              const float* __restrict__ W3, const float* __restrict__ b3,
                              const float* __restrict__ scale_ptr, int B)
{
    const int i  = blockIdx.y;
    const int ty = threadIdx.y;
    const int k  = threadIdx.x;
    const int b  = blockIdx.x * 4 + ty;
    const bool valid = (b < B);

    __shared__ float sh_h[4][64];
    __shared__ float sh_bd[4][5];

    float h = 0.0f;
    if (valid) {
        const float* p = positions + (size_t)b * 6 + (c_SIDE[i] ? 0 : 3);
        float p0 = p[0] * 100.0f, p1 = p[1] * 100.0f, p2 = p[2] * 100.0f;
        const float* w1 = W1 + (size_t)i * 3 * 64;
        h = fmaf(p0, w1[k], fmaf(p1, w1[64 + k], fmaf(p2, w1[128 + k], b1[i * 64 + k])));
        h = fmaxf(h, 0.0f);
    }
    sh_h[ty][k] = h;
    __syncthreads();

    float acc;
    {
        const float* w2 = W2 + (size_t)i * 64 * 64 + k;
        float a0 = b2[i * 64 + k], a1 = 0.0f;
        #pragma unroll 8
        for (int hh = 0; hh < 64; hh += 2) {
            a0 = fmaf(sh_h[ty][hh],     w2[hh * 64],        a0);
            a1 = fmaf(sh_h[ty][hh + 1], w2[(hh + 1) * 64],  a1);
        }
        acc = fmaxf(a0 + a1, 0.0f);
    }
    __syncthreads();
    sh_h[ty][k] = acc;
    __syncthreads();

    if (k < 5) {
        const float* w3 = W3 + (size_t)i * 64 * 5 + k;
        float o0 = b3[i * 5 + k], o1 = 0.0f;
        #pragma unroll 8
        for (int hh = 0; hh < 64; hh += 2) {
            o0 = fmaf(sh_h[ty][hh],     w3[hh * 5],       o0);
            o1 = fmaf(sh_h[ty][hh + 1], w3[(hh + 1) * 5], o1);
        }
        sh_bd[ty][k] = o0 + o1;
    }
    __syncthreads();

    if (k == 0 && valid) {
        float bd0 = sh_bd[ty][0], bd1 = sh_bd[ty][1], bd2 = sh_bd[ty][2];
        float bd3 = sh_bd[ty][3], bd4 = sh_bd[ty][4];
        float scale = *scale_ptr;

        float y  = sigmoidf_(bd0) + c_START_Y[i];
        float x  = sigmoidf_(bd1) + c_START_X[i];
        float s  = (bd2 + 0.05f) * scale;
        float a  = 0.5f + sigmoidf_(bd3) * 1.5f;
        float th = sigmoidf_(bd4) * 3.14159265358979323846f;

        float sa = s * a + 1e-6f;
        float sb = s / (a + 1e-6f) + 1e-6f;
        float A  = 0.5f / (sa * sa);
        float Bq = 0.5f / (sb * sb);

        float sn = __sinf(th);          // th in [0, pi]
        float c  = __cosf(th);

        const float L = 1.4426950408889634f;
        float al = -L * (A * c * c + Bq * sn * sn);
        float be = -L * (A * sn * sn + Bq * c * c);
        float ga = -2.0f * L * (A - Bq) * c * sn;

        float* o = g_params + ((size_t)i * B + b) * 5;
        o[0] = y; o[1] = x; o[2] = al; o[3] = be; o[4] = ga;
    }
}

// ---------------------------------------------------------------------------
// Splat via multiplicative forward recurrence (T = 256 only), step-outer /
// blob-group-inner for ILP: 2 groups of 4 blobs, all 4 recurrence chains live
// simultaneously; per step k: 4 blend fma2 + 8 independent update mul2.
// Blend order per pixel remains blob 0..7 (group A fully applied, then B) —
// arithmetic identical to the R13-passing kernel.
// ---------------------------------------------------------------------------
__global__ void __launch_bounds__(256) splat_rec256(float* __restrict__ out,
                                                    int B, int T, float invT)
{
    const int b   = blockIdx.y;
    const int tid = threadIdx.x;

    __shared__ float  sp[NB * 5];
    __shared__ float4 rowtab[16][NB];            // {K1, K0, cd, K2}
    __shared__ __align__(16) float qds[NB];      // qd per blob
    __shared__ __align__(16) float rhos[NB];     // rho per blob

    if (tid < NB * 5) {
        int i = tid / 5, f = tid - i * 5;
        sp[tid] = g_params[((size_t)i * B + b) * 5 + f];
    }
    __syncthreads();

    if (tid < 128) {
        const int r = tid >> 3;          // row-in-block 0..15
        const int i = tid & 7;           // blob
        float y  = sp[i * 5 + 0];
        float x  = sp[i * 5 + 1];
        float al = sp[i * 5 + 2];
        float be = sp[i * 5 + 3];
        float ga = sp[i * 5 + 4];
        float rowc = ((float)(blockIdx.x * 16 + r) + 0.5f) * invT;
        float dy = rowc - y;
        float K2 = be;
        float K1 = fmaf(ga, dy, -2.0f * be * x);
        float mm = fmaf(al, dy, -(ga * x));
        float K0 = fmaf(mm, dy, be * x * x);
        // d(w) = e(w+2D) - e(w) = (4 K2 D) w + (4 K2 D^2 + 2 K1 D)
        float cd = fmaf(4.0f * K2 * invT, invT, 2.0f * K1 * invT);
        rowtab[r][i] = make_float4(K1, K0, cd, K2);
        if (r == 0) {
            qds[i]  = 4.0f * K2 * invT;
            rhos[i] = exp2f(8.0f * K2 * invT * invT);   // in (0, 1]
        }
    }
    __syncthreads();

    const int lane   = tid & 31;
    const int rr     = ((tid >> 5) << 1) | (lane >> 4);   // row-in-block 0..15
    const int lane16 = lane & 15;
    const int row    = blockIdx.x * 16 + rr;
    const int seg    = lane16 * 16;                       // first pixel of segment

    const float w0 = ((float)seg + 0.5f) * invT;
    const float w1 = w0 + invT;

    const float4* qd4 = reinterpret_cast<const float4*>(qds);
    const float4* rh4 = reinterpret_cast<const float4*>(rhos);

    ull img[8];
    #pragma unroll
    for (int k = 0; k < 8; k++) img[k] = 0ull;

    #pragma unroll
    for (int grp = 0; grp < 2; grp++) {
        const int base = grp * 4;
        float4 qv = qd4[grp];
        float4 rv = rh4[grp];
        float qdi[4] = {qv.x, qv.y, qv.z, qv.w};
        float rhi[4] = {rv.x, rv.y, rv.z, rv.w};

        ull g_[4], m_[4], r_[4];
        #pragma unroll
        for (int i = 0; i < 4; i++) {
            float4 rt = rowtab[rr][base + i];    // K1, K0, cd, K2
            float e0 = fmaf(fmaf(rt.w, w0, rt.x), w0, rt.y);
            float e1 = fmaf(fmaf(rt.w, w1, rt.x), w1, rt.y);
            float d0 = fminf(fmaf(qdi[i], w0, rt.z), 126.0f);
            float d1 = fminf(fmaf(qdi[i], w1, rt.z), 126.0f);
            g_[i] = pk2(ex2_(e0), ex2_(e1));
            m_[i] = pk2(ex2_(d0), ex2_(d1));
            r_[i] = pk2(rhi[i], rhi[i]);
        }

        #pragma unroll
        for (int k = 0; k < 8; k++) {
            #pragma unroll
            for (int i = 0; i < 4; i++)
                img[k] = fma2(img[k], g_[i], g_[i]);   // blend order preserved
            if (k < 7) {
                #pragma unroll
                for (int i = 0; i < 4; i++) {
                    g_[i] = mul2(g_[i], m_[i]);
                    m_[i] = mul2(m_[i], r_[i]);
                }
            }
        }
    }

    float* orow = out + ((size_t)b * T + row) * T + seg;
    #pragma unroll
    for (int j = 0; j < 4; j++) {
        float x0, x1, x2, x3;
        upk2(x0, x1, img[2 * j]);
        upk2(x2, x3, img[2 * j + 1]);
        reinterpret_cast<float4*>(orow)[j] = make_float4(x0, x1, x2, x3);
    }
}

// ---------------------------------------------------------------------------
// Generic fallback splat (round-2 kernel, known correct for any T).
// ---------------------------------------------------------------------------
__global__ void __launch_bounds__(256) splat_kernel(float* __restrict__ out,
                                                    int B, int T, float invT)
{
    const int b    = blockIdx.y;
    const int tid  = threadIdx.x;
    const int lane = tid & 31;
    const int r    = tid >> 5;
    const int row  = blockIdx.x * 8 + r;

    __shared__ float sp[NB * 5];
    if (tid < NB * 5) {
        int i = tid / 5, f = tid - i * 5;
        sp[tid] = g_params[((size_t)i * B + b) * 5 + f];
    }
    __syncthreads();
    if (row >= T) return;

    const float rowc = ((float)row + 0.5f) * invT;

    float K2[NB], K1[NB], K0[NB];
    #pragma unroll
    for (int i = 0; i < NB; i++) {
        float y  = sp[i * 5 + 0];
        float x  = sp[i * 5 + 1];
        float al = sp[i * 5 + 2];
        float be = sp[i * 5 + 3];
        float ga = sp[i * 5 + 4];
        float dy = rowc - y;
        K2[i] = be;
        K1[i] = fmaf(ga, dy, -2.0f * be * x);
        float m = fmaf(al, dy, -(ga * x));
        K0[i] = fmaf(m, dy, be * x * x);
    }

    float* orow = out + ((size_t)b * T + row) * T;
    const int nj = (T + 31) >> 5;

    for (int j = 0; j < nj; j++) {
        int col = lane + (j << 5);
        if (col >= T) break;
        float w = ((float)col + 0.5f) * invT;
        float img = 0.0f;
        #pragma unroll
        for (int i = 0; i < NB; i++) {
            float e = fmaf(fmaf(K2[i], w, K1[i]), w, K0[i]);
            float cur = ex2_(e);
            img = fmaf(img, cur, cur);
        }
        orow[col] = img;
    }
}

// ---------------------------------------------------------------------------
extern "C" void kernel_launch(void* const* d_in, const int* in_sizes, int n_in,
                              void* d_out, int out_size)
{
    const float* positions = (const float*)d_in[0];
    const float* W1 = (const float*)d_in[1];
    const float* b1 = (const float*)d_in[2];
    const float* W2 = (const float*)d_in[3];
    const float* b2 = (const float*)d_in[4];
    const float* W3 = (const float*)d_in[5];
    const float* b3 = (const float*)d_in[6];
    const float* scale = (const float*)d_in[n_in - 1];

    int B = in_sizes[0] / 6;
    if (B > MAX_B) B = MAX_B;
    int T = (int)(sqrt((double)out_size / (double)B) + 0.5);
    float invT = 1.0f / (float)T;

    dim3 egrid((B + 3) / 4, NB);
    dim3 eblock(64, 4);
    encode_kernel<<<egrid, eblock>>>(positions, W1, b1, W2, b2, W3, b3, scale, B);

    if (T == 256) {
        dim3 sgrid(16, B);                // 16 rows per block
        splat_rec256<<<sgrid, 256>>>((float*)d_out, B, T, invT);
    } else {
        dim3 sgrid((T + 7) / 8, B);
        splat_kernel<<<sgrid, 256>>>((float*)d_out, B, T, invT);
    }
}

// round 15
// speedup vs baseline: 1.6341x; 1.0022x over previous
#include <cuda_runtime.h>
#include <math.h>

#define NB 8

__constant__ float c_START_Y[NB] = {0.1f, 0.2f, 0.3f, 0.4f, 0.5f, 0.6f, 0.7f, 0.8f};
__constant__ float c_START_X[NB] = {0.8f, 0.7f, 0.6f, 0.5f, 0.4f, 0.3f, 0.2f, 0.1f};
__constant__ int   c_SIDE[NB]    = {1, 0, 1, 0, 1, 0, 1, 0};

#define MAX_B 4096
__device__ float g_params[NB * MAX_B * 5];

__device__ __forceinline__ float sigmoidf_(float v) {
    return 1.0f / (1.0f + __expf(-v));
}

// ---------------- f32x2 packed helpers (Blackwell) --------------------------
typedef unsigned long long ull;
__device__ __forceinline__ ull pk2(float x, float y) {
    ull r; asm("mov.b64 %0, {%1,%2};" : "=l"(r) : "f"(x), "f"(y)); return r;
}
__device__ __forceinline__ void upk2(float& x, float& y, ull v) {
    asm("mov.b64 {%0,%1}, %2;" : "=f"(x), "=f"(y) : "l"(v));
}
__device__ __forceinline__ ull fma2(ull a, ull b, ull c) {
    ull d; asm("fma.rn.f32x2 %0, %1, %2, %3;" : "=l"(d) : "l"(a), "l"(b), "l"(c)); return d;
}
__device__ __forceinline__ ull mul2(ull a, ull b) {
    ull d; asm("mul.rn.f32x2 %0, %1, %2;" : "=l"(d) : "l"(a), "l"(b)); return d;
}
__device__ __forceinline__ float ex2_(float v) {
    float r; asm("ex2.approx.ftz.f32 %0, %1;" : "=f"(r) : "f"(v)); return r;
}

// ---------------------------------------------------------------------------
// Encode: per-blob MLP with all weights staged in shared memory (L2-latency ->
// smem-latency for the GEMV loops). Math identical to the R14-passing version.
// block = (64, 4), grid = (B/4, NB).
// ---------------------------------------------------------------------------
__global__ void encode_kernel(const float* __restrict__ positions,
                              const float* __restrict__ W1, const float* __restrict__ b1,
                              const float* __restrict__ W2, const float* __restrict__ b2,
                              const float* __restrict__ W3, const float* __restrict__ b3,
                              const float* __restrict__ scale_ptr, int B)
{
    const int i   = blockIdx.y;
    const int ty  = threadIdx.y;
    const int k   = threadIdx.x;
    const int tid = ty * 64 + k;
    const int b   = blockIdx.x * 4 + ty;
    const bool valid = (b < B);

    __shared__ float w1s[3 * 64];
    __shared__ float b1s[64];
    __shared__ float w2s[64 * 64];
    __shared__ float b2s[64];
    __shared__ float w3s[64 * 5];
    __shared__ float b3s[8];
    __shared__ float sh_h[4][64];
    __shared__ float sh_bd[4][5];

    // ---- stage weights (coalesced) ----
    {
        const float* w2g = W2 + (size_t)i * 64 * 64;
        #pragma unroll
        for (int j = tid; j < 64 * 64; j += 256) w2s[j] = w2g[j];
        if (tid < 3 * 64) w1s[tid] = W1[(size_t)i * 3 * 64 + tid];
        if (tid < 64)  b1s[tid] = b1[i * 64 + tid];
        if (tid < 64)  b2s[tid] = b2[i * 64 + tid];
        if (tid < 64 * 5) {
            int base = 0;
            for (int j = tid; j < 64 * 5; j += 256) { w3s[j] = W3[(size_t)i * 64 * 5 + j]; base = j; }
            (void)base;
        }
        if (tid < 5) b3s[tid] = b3[i * 5 + tid];
    }
    __syncthreads();

    // ---- layer 1: 3 -> 64, relu ----
    float h = 0.0f;
    if (valid) {
        const float* p = positions + (size_t)b * 6 + (c_SIDE[i] ? 0 : 3);
        float p0 = p[0] * 100.0f, p1 = p[1] * 100.0f, p2 = p[2] * 100.0f;
        h = fmaf(p0, w1s[k], fmaf(p1, w1s[64 + k], fmaf(p2, w1s[128 + k], b1s[k])));
        h = fmaxf(h, 0.0f);
    }
    sh_h[ty][k] = h;
    __syncthreads();

    // ---- layer 2: 64 -> 64, relu (dual accumulators) ----
    float acc;
    {
        float a0 = b2s[k], a1 = 0.0f;
        #pragma unroll 8
        for (int hh = 0; hh < 64; hh += 2) {
            a0 = fmaf(sh_h[ty][hh],     w2s[hh * 64 + k],       a0);
            a1 = fmaf(sh_h[ty][hh + 1], w2s[(hh + 1) * 64 + k], a1);
        }
        acc = fmaxf(a0 + a1, 0.0f);
    }
    __syncthreads();
    sh_h[ty][k] = acc;
    __syncthreads();

    // ---- layer 3: 64 -> 5 ----
    if (k < 5) {
        float o0 = b3s[k], o1 = 0.0f;
        #pragma unroll 8
        for (int hh = 0; hh < 64; hh += 2) {
            o0 = fmaf(sh_h[ty][hh],     w3s[hh * 5 + k],       o0);
            o1 = fmaf(sh_h[ty][hh + 1], w3s[(hh + 1) * 5 + k], o1);
        }
        sh_bd[ty][k] = o0 + o1;
    }
    __syncthreads();

    if (k == 0 && valid) {
        float bd0 = sh_bd[ty][0], bd1 = sh_bd[ty][1], bd2 = sh_bd[ty][2];
        float bd3 = sh_bd[ty][3], bd4 = sh_bd[ty][4];
        float scale = *scale_ptr;

        float y  = sigmoidf_(bd0) + c_START_Y[i];
        float x  = sigmoidf_(bd1) + c_START_X[i];
        float s  = (bd2 + 0.05f) * scale;
        float a  = 0.5f + sigmoidf_(bd3) * 1.5f;
        float th = sigmoidf_(bd4) * 3.14159265358979323846f;

        float sa = s * a + 1e-6f;
        float sb = s / (a + 1e-6f) + 1e-6f;
        float A  = 0.5f / (sa * sa);
        float Bq = 0.5f / (sb * sb);

        float sn = __sinf(th);          // th in [0, pi]
        float c  = __cosf(th);

        const float L = 1.4426950408889634f;
        float al = -L * (A * c * c + Bq * sn * sn);
        float be = -L * (A * sn * sn + Bq * c * c);
        float ga = -2.0f * L * (A - Bq) * c * sn;

        float* o = g_params + ((size_t)i * B + b) * 5;
        o[0] = y; o[1] = x; o[2] = al; o[3] = be; o[4] = ga;
    }
}

// ---------------------------------------------------------------------------
// Splat via multiplicative forward recurrence (T = 256 only), step-outer /
// blob-group-inner (R14 math, byte-identical). Block = 128 threads = 8 rows,
// grid = (32, B): finer wave granularity at unchanged occupancy.
// ---------------------------------------------------------------------------
__global__ void __launch_bounds__(128) splat_rec256(float* __restrict__ out,
                                                    int B, int T, float invT)
{
    const int b   = blockIdx.y;
    const int tid = threadIdx.x;

    __shared__ float  sp[NB * 5];
    __shared__ float4 rowtab[8][NB];             // {K1, K0, cd, K2}
    __shared__ __align__(16) float qds[NB];      // qd per blob
    __shared__ __align__(16) float rhos[NB];     // rho per blob

    if (tid < NB * 5) {
        int i = tid / 5, f = tid - i * 5;
        sp[tid] = g_params[((size_t)i * B + b) * 5 + f];
    }
    __syncthreads();

    if (tid < 64) {
        const int r = tid >> 3;          // row-in-block 0..7
        const int i = tid & 7;           // blob
        float y  = sp[i * 5 + 0];
        float x  = sp[i * 5 + 1];
        float al = sp[i * 5 + 2];
        float be = sp[i * 5 + 3];
        float ga = sp[i * 5 + 4];
        float rowc = ((float)(blockIdx.x * 8 + r) + 0.5f) * invT;
        float dy = rowc - y;
        float K2 = be;
        float K1 = fmaf(ga, dy, -2.0f * be * x);
        float mm = fmaf(al, dy, -(ga * x));
        float K0 = fmaf(mm, dy, be * x * x);
        // d(w) = e(w+2D) - e(w) = (4 K2 D) w + (4 K2 D^2 + 2 K1 D)
        float cd = fmaf(4.0f * K2 * invT, invT, 2.0f * K1 * invT);
        rowtab[r][i] = make_float4(K1, K0, cd, K2);
        if (r == 0) {
            qds[i]  = 4.0f * K2 * invT;
            rhos[i] = exp2f(8.0f * K2 * invT * invT);   // in (0, 1]
        }
    }
    __syncthreads();

    const int lane   = tid & 31;
    const int rr     = ((tid >> 5) << 1) | (lane >> 4);   // row-in-block 0..7
    const int lane16 = lane & 15;
    const int row    = blockIdx.x * 8 + rr;
    const int seg    = lane16 * 16;                       // first pixel of segment

    const float w0 = ((float)seg + 0.5f) * invT;
    const float w1 = w0 + invT;

    const float4* qd4 = reinterpret_cast<const float4*>(qds);
    const float4* rh4 = reinterpret_cast<const float4*>(rhos);

    ull img[8];
    #pragma unroll
    for (int k = 0; k < 8; k++) img[k] = 0ull;

    #pragma unroll
    for (int grp = 0; grp < 2; grp++) {
        const int base = grp * 4;
        float4 qv = qd4[grp];
        float4 rv = rh4[grp];
        float qdi[4] = {qv.x, qv.y, qv.z, qv.w};
        float rhi[4] = {rv.x, rv.y, rv.z, rv.w};

        ull g_[4], m_[4], r_[4];
        #pragma unroll
        for (int i = 0; i < 4; i++) {
            float4 rt = rowtab[rr][base + i];    // K1, K0, cd, K2
            float e0 = fmaf(fmaf(rt.w, w0, rt.x), w0, rt.y);
            float e1 = fmaf(fmaf(rt.w, w1, rt.x), w1, rt.y);
            float d0 = fminf(fmaf(qdi[i], w0, rt.z), 126.0f);
            float d1 = fminf(fmaf(qdi[i], w1, rt.z), 126.0f);
            g_[i] = pk2(ex2_(e0), ex2_(e1));
            m_[i] = pk2(ex2_(d0), ex2_(d1));
            r_[i] = pk2(rhi[i], rhi[i]);
        }

        #pragma unroll
        for (int k = 0; k < 8; k++) {
            #pragma unroll
            for (int i = 0; i < 4; i++)
                img[k] = fma2(img[k], g_[i], g_[i]);   // blend order preserved
            if (k < 7) {
                #pragma unroll
                for (int i = 0; i < 4; i++) {
                    g_[i] = mul2(g_[i], m_[i]);
                    m_[i] = mul2(m_[i], r_[i]);
                }
            }
        }
    }

    float* orow = out + ((size_t)b * T + row) * T + seg;
    #pragma unroll
    for (int j = 0; j < 4; j++) {
        float x0, x1, x2, x3;
        upk2(x0, x1, img[2 * j]);
        upk2(x2, x3, img[2 * j + 1]);
        reinterpret_cast<float4*>(orow)[j] = make_float4(x0, x1, x2, x3);
    }
}

// ---------------------------------------------------------------------------
// Generic fallback splat (round-2 kernel, known correct for any T).
// ---------------------------------------------------------------------------
__global__ void __launch_bounds__(256) splat_kernel(float* __restrict__ out,
                                                    int B, int T, float invT)
{
    const int b    = blockIdx.y;
    const int tid  = threadIdx.x;
    const int lane = tid & 31;
    const int r    = tid >> 5;
    const int row  = blockIdx.x * 8 + r;

    __shared__ float sp[NB * 5];
    if (tid < NB * 5) {
        int i = tid / 5, f = tid - i * 5;
        sp[tid] = g_params[((size_t)i * B + b) * 5 + f];
    }
    __syncthreads();
    if (row >= T) return;

    const float rowc = ((float)row + 0.5f) * invT;

    float K2[NB], K1[NB], K0[NB];
    #pragma unroll
    for (int i = 0; i < NB; i++) {
        float y  = sp[i * 5 + 0];
        float x  = sp[i * 5 + 1];
        float al = sp[i * 5 + 2];
        float be = sp[i * 5 + 3];
        float ga = sp[i * 5 + 4];
        float dy = rowc - y;
        K2[i] = be;
        K1[i] = fmaf(ga, dy, -2.0f * be * x);
        float m = fmaf(al, dy, -(ga * x));
        K0[i] = fmaf(m, dy, be * x * x);
    }

    float* orow = out + ((size_t)b * T + row) * T;
    const int nj = (T + 31) >> 5;

    for (int j = 0; j < nj; j++) {
        int col = lane + (j << 5);
        if (col >= T) break;
        float w = ((float)col + 0.5f) * invT;
        float img = 0.0f;
        #pragma unroll
        for (int i = 0; i < NB; i++) {
            float e = fmaf(fmaf(K2[i], w, K1[i]), w, K0[i]);
            float cur = ex2_(e);
            img = fmaf(img, cur, cur);
        }
        orow[col] = img;
    }
}

// ---------------------------------------------------------------------------
extern "C" void kernel_launch(void* const* d_in, const int* in_sizes, int n_in,
                              void* d_out, int out_size)
{
    const float* positions = (const float*)d_in[0];
    const float* W1 = (const float*)d_in[1];
    const float* b1 = (const float*)d_in[2];
    const float* W2 = (const float*)d_in[3];
    const float* b2 = (const float*)d_in[4];
    const float* W3 = (const float*)d_in[5];
    const float* b3 = (const float*)d_in[6];
    const float* scale = (const float*)d_in[n_in - 1];

    int B = in_sizes[0] / 6;
    if (B > MAX_B) B = MAX_B;
    int T = (int)(sqrt((double)out_size / (double)B) + 0.5);
    float invT = 1.0f / (float)T;

    dim3 egrid((B + 3) / 4, NB);
    dim3 eblock(64, 4);
    encode_kernel<<<egrid, eblock>>>(positions, W1, b1, W2, b2, W3, b3, scale, B);

    if (T == 256) {
        dim3 sgrid(32, B);                // 8 rows per 128-thread block
        splat_rec256<<<sgrid, 128>>>((float*)d_out, B, T, invT);
    } else {
        dim3 sgrid((T + 7) / 8, B);
        splat_kernel<<<sgrid, 256>>>((float*)d_out, B, T, invT);
    }
}